// round 15
// baseline (speedup 1.0000x reference)
#include <cuda_runtime.h>
#include <cuda_bf16.h>
#include <cuda_fp16.h>
#include <cstdint>
#include <math.h>

// Problem constants (fixed by the dataset)
#define NS 100000
#define NE 100000
#define EDG 1600000
#define D 256
#define H 8
#define HD 32
#define FEAT 64
#define DFF 512

#define SCAN_B 1024
#define NBLK ((NS + SCAN_B - 1) / SCAN_B)   // 98

// smem tile geometry: 32 elems of k per row, padded to 40 (80 B)
#define KP 40
#define ROWB 80
#define MATB (128 * ROWB)          // 10240 B per matrix
#define SMEM_BF3 (2 * 4 * MATB)    // 81920 B: bf16 3-pass, 2 stages (Ah,Al,Bh,Bl)
#define SMEM_FP1 (3 * 2 * MATB)    // 61440 B: fp16 1-pass, 3 stages (A,B)

typedef __nv_bfloat16 bf16;
typedef __half f16;

// ---------------- device scratch (no allocations allowed) ----------------
__device__ f16   g_zf[(size_t)NE * D];   // z in fp16 (gathered by attention)
__device__ float g_df[(size_t)NS * D];
__device__ float g_x[(size_t)NS * D];
__device__ float g_xs[(size_t)NS * D];   // s @ proj_w[256:] + b (side stream)
// bf16 split (z path)
__device__ bf16 g_eh[(size_t)NE * D], g_el[(size_t)NE * D];
__device__ bf16 g_wzh[256 * 256], g_wzl[256 * 256];
// fp16 rn
__device__ f16 g_ff[(size_t)NS * FEAT];  // dst_feat fp16
__device__ f16 g_wd16[256 * 64];         // dstfeat_w transposed fp16
__device__ f16 g_sf[(size_t)NS * D];
__device__ f16 g_hf[(size_t)NS * D];
__device__ f16 g_xnf[(size_t)NS * D];
__device__ f16 g_tf[(size_t)NS * DFF];
// fp16 plain transposed weights Wt[n][k]
__device__ f16 g_pw[256 * 512];
__device__ f16 g_w1[512 * 256];
__device__ f16 g_w2[256 * 512];
// CSR
__device__ int g_counts[NS];
__device__ int g_offsets[NS + 1];
__device__ int g_cursor[NS];
__device__ int g_csr_src[EDG];
__device__ int g_bsum[NBLK];

// ---------------- small helpers ----------------
__device__ __forceinline__ float gelu_fast(float x) {
    const float c = 0.7978845608028654f;
    float u = c * (x + 0.044715f * x * x * x);
    float e = __expf(2.0f * u);
    float th = 1.0f - 2.0f / (e + 1.0f);
    return 0.5f * x * (1.0f + th);
}
__device__ __forceinline__ uint32_t smem_u32(const void* p) {
    uint32_t a;
    asm("{ .reg .u64 t; cvta.to.shared.u64 t, %1; cvt.u32.u64 %0, t; }" : "=r"(a) : "l"(p));
    return a;
}
__device__ __forceinline__ void ldm_x4(uint32_t* r, uint32_t addr) {
    asm volatile("ldmatrix.sync.aligned.m8n8.x4.shared.b16 {%0,%1,%2,%3}, [%4];"
                 : "=r"(r[0]), "=r"(r[1]), "=r"(r[2]), "=r"(r[3]) : "r"(addr));
}
__device__ __forceinline__ uint32_t pk2(bf16 a, bf16 b) {
    __nv_bfloat162 t(a, b); return *(uint32_t*)&t;
}
__device__ __forceinline__ uint32_t pk2(f16 a, f16 b) {
    __half2 t(a, b); return *(uint32_t*)&t;
}
__device__ __forceinline__ void split2(float x, bf16& hi, bf16& lo) {
    hi = __float2bfloat16_rn(x);
    lo = __float2bfloat16_rn(x - __bfloat162float(hi));
}
template <typename T>
__device__ __forceinline__ void mma_t(float* c, const uint32_t* a, const uint32_t* b);
template <>
__device__ __forceinline__ void mma_t<bf16>(float* c, const uint32_t* a, const uint32_t* b) {
    asm volatile(
        "mma.sync.aligned.m16n8k16.row.col.f32.bf16.bf16.f32 "
        "{%0,%1,%2,%3}, {%4,%5,%6,%7}, {%8,%9}, {%0,%1,%2,%3};"
        : "+f"(c[0]), "+f"(c[1]), "+f"(c[2]), "+f"(c[3])
        : "r"(a[0]), "r"(a[1]), "r"(a[2]), "r"(a[3]), "r"(b[0]), "r"(b[1]));
}
template <>
__device__ __forceinline__ void mma_t<f16>(float* c, const uint32_t* a, const uint32_t* b) {
    asm volatile(
        "mma.sync.aligned.m16n8k16.row.col.f32.f16.f16.f32 "
        "{%0,%1,%2,%3}, {%4,%5,%6,%7}, {%8,%9}, {%0,%1,%2,%3};"
        : "+f"(c[0]), "+f"(c[1]), "+f"(c[2]), "+f"(c[3])
        : "r"(a[0]), "r"(a[1]), "r"(a[2]), "r"(a[3]), "r"(b[0]), "r"(b[1]));
}
__device__ __forceinline__ void cpa16(uint32_t dst, const void* src, bool pred) {
    int sz = pred ? 16 : 0;
    asm volatile("cp.async.cg.shared.global [%0], [%1], 16, %2;"
                 :: "r"(dst), "l"(src), "r"(sz) : "memory");
}

// ---------------- conversion kernels ----------------
__global__ void act_split_bf(const float* __restrict__ in, bf16* __restrict__ hi,
                             bf16* __restrict__ lo, int n) {
    int i = 4 * (blockIdx.x * blockDim.x + threadIdx.x);
    if (i >= n) return;
    float4 v = *(const float4*)(in + i);
    bf16 h0, l0, h1, l1, h2, l2, h3, l3;
    split2(v.x, h0, l0); split2(v.y, h1, l1);
    split2(v.z, h2, l2); split2(v.w, h3, l3);
    *(uint2*)(hi + i) = make_uint2(pk2(h0, h1), pk2(h2, h3));
    *(uint2*)(lo + i) = make_uint2(pk2(l0, l1), pk2(l2, l3));
}
__global__ void act_rn16(const float* __restrict__ in, f16* __restrict__ o, int n) {
    int i = 4 * (blockIdx.x * blockDim.x + threadIdx.x);
    if (i >= n) return;
    float4 v = *(const float4*)(in + i);
    *(uint2*)(o + i) = make_uint2(pk2(__float2half_rn(v.x), __float2half_rn(v.y)),
                                  pk2(__float2half_rn(v.z), __float2half_rn(v.w)));
}
__global__ void wsplit_t16(const float* __restrict__ w, f16* __restrict__ o, int K, int N) {
    int idx = blockIdx.x * blockDim.x + threadIdx.x;
    if (idx >= K * N) return;
    int k = idx / N, n = idx % N;
    o[(size_t)n * K + k] = __float2half_rn(w[idx]);
}
// per-head weight (H, K, HD) -> bf16 split Wt[256][K]
__global__ void repack_split(const float* __restrict__ w, bf16* __restrict__ hi,
                             bf16* __restrict__ lo, int K) {
    int idx = blockIdx.x * blockDim.x + threadIdx.x;
    if (idx >= K * 256) return;
    int n = idx / K, k = idx % K;
    bf16 h, l;
    split2(w[(n >> 5) * (K * 32) + k * 32 + (n & 31)], h, l);
    hi[idx] = h;
    lo[idx] = l;
}
// per-head weight (H, K, HD) -> fp16 rn Wt[256][K]
__global__ void repack_rn16(const float* __restrict__ w, f16* __restrict__ o, int K) {
    int idx = blockIdx.x * blockDim.x + threadIdx.x;
    if (idx >= K * 256) return;
    int n = idx / K, k = idx % K;
    o[idx] = __float2half_rn(w[(n >> 5) * (K * 32) + k * 32 + (n & 31)]);
}

// ================= multistage cp.async GEMM =================
// PASSES==3 (bf16): Ah*Bh + Al*Bh + Ah*Bl.  PASSES==1 (fp16): A*B plain rn.
template <typename T, int PASSES, int NSTAGE, int ACT, bool BIAS, bool RES, bool OHALF>
__global__ void __launch_bounds__(256, 2) mma_gemm(
    const T* __restrict__ Ah0, const T* __restrict__ Al0, int lda0,
    const T* __restrict__ Ah1, const T* __restrict__ Al1, int lda1, int ksplit,
    const T* __restrict__ Bh, const T* __restrict__ Bl, int ldbk,
    const float* __restrict__ bias,
    const float* __restrict__ res, int ldr,
    float* __restrict__ C, f16* __restrict__ Cf, int ldc,
    int M, int K)
{
    constexpr int NMAT = (PASSES == 3) ? 4 : 2;
    constexpr int STB = NMAT * MATB;
    constexpr int BOFF = (PASSES == 3) ? 2 * MATB : MATB;
    extern __shared__ char dsm[];
    uint32_t sb = smem_u32(dsm);

    int t = threadIdx.x;
    int lane = t & 31, wid = t >> 5;
    int m0 = blockIdx.y * 128;
    int n0 = blockIdx.x * 128;
    int wm = wid & 3;
    int wn = wid >> 2;

    float acc[2][8][4];
#pragma unroll
    for (int i = 0; i < 2; i++)
#pragma unroll
        for (int j = 0; j < 8; j++)
#pragma unroll
            for (int q = 0; q < 4; q++) acc[i][j][q] = 0.0f;

    uint32_t a_off = (uint32_t)(((wm * 32 + (lane & 15)) * KP + (lane >> 4) * 8) * 2);
    uint32_t b_off = (uint32_t)(((wn * 64 + (lane & 7) + (lane >> 4) * 8) * KP
                                 + ((lane >> 3) & 1) * 8) * 2);

    int p_row = t >> 1;
    int p_c0 = (t & 1) * 2;
    bool a_ok = (m0 + p_row) < M;
    const int KT = K >> 5;

    auto prefetch = [&](int kt) {
        if (kt < KT) {
            int k0 = kt * 32;
            int stage = kt % NSTAGE;
            const T *AhS, *AlS; int lda, koff;
            if (k0 < ksplit) { AhS = Ah0; AlS = Al0; lda = lda0; koff = k0; }
            else             { AhS = Ah1; AlS = Al1; lda = lda1; koff = k0 - ksplit; }
            const T* pah = AhS + (size_t)(m0 + p_row) * lda + koff;
            const T* pbh = Bh + (size_t)(n0 + p_row) * ldbk + k0;
            uint32_t base = sb + stage * STB + p_row * ROWB;
#pragma unroll
            for (int ci = 0; ci < 2; ci++) {
                int c = p_c0 + ci;
                cpa16(base + c * 16,        pah + c * 8, a_ok);
                cpa16(base + BOFF + c * 16, pbh + c * 8, true);
                if (PASSES == 3) {
                    const T* pal = AlS + (size_t)(m0 + p_row) * lda + koff;
                    const T* pbl = Bl + (size_t)(n0 + p_row) * ldbk + k0;
                    cpa16(base + MATB + c * 16,     pal + c * 8, a_ok);
                    cpa16(base + 3 * MATB + c * 16, pbl + c * 8, true);
                }
            }
        }
        asm volatile("cp.async.commit_group;" ::: "memory");
    };

#pragma unroll
    for (int s = 0; s < NSTAGE - 1; s++) prefetch(s);

    for (int kt = 0; kt < KT; kt++) {
        if (NSTAGE == 2) asm volatile("cp.async.wait_group 0;" ::: "memory");
        else             asm volatile("cp.async.wait_group 1;" ::: "memory");
        __syncthreads();

        prefetch(kt + NSTAGE - 1);

        uint32_t s0 = sb + (kt % NSTAGE) * STB;
        uint32_t sAh = s0, sBh = s0 + BOFF;

#pragma unroll
        for (int ks = 0; ks < 2; ks++) {
            uint32_t koffb = (uint32_t)(ks * 32);
            uint32_t a_hi[2][4], b[4][4];
            ldm_x4(a_hi[0], sAh + a_off + koffb);
            ldm_x4(a_hi[1], sAh + a_off + koffb + 16 * KP * 2);
#pragma unroll
            for (int ni2 = 0; ni2 < 4; ni2++)
                ldm_x4(b[ni2], sBh + b_off + koffb + ni2 * 16 * KP * 2);
            // pass 1: Ah * Bh
#pragma unroll
            for (int mi = 0; mi < 2; mi++)
#pragma unroll
                for (int ni = 0; ni < 8; ni++)
                    mma_t<T>(acc[mi][ni], a_hi[mi], &b[ni >> 1][(ni & 1) * 2]);
            if (PASSES == 3) {
                uint32_t sAl = s0 + MATB, sBl = s0 + 3 * MATB;
                uint32_t a_lo[2][4];
                ldm_x4(a_lo[0], sAl + a_off + koffb);
                ldm_x4(a_lo[1], sAl + a_off + koffb + 16 * KP * 2);
#pragma unroll
                for (int mi = 0; mi < 2; mi++)
#pragma unroll
                    for (int ni = 0; ni < 8; ni++)
                        mma_t<T>(acc[mi][ni], a_lo[mi], &b[ni >> 1][(ni & 1) * 2]);
#pragma unroll
                for (int ni2 = 0; ni2 < 4; ni2++)
                    ldm_x4(b[ni2], sBl + b_off + koffb + ni2 * 16 * KP * 2);
#pragma unroll
                for (int mi = 0; mi < 2; mi++)
#pragma unroll
                    for (int ni = 0; ni < 8; ni++)
                        mma_t<T>(acc[mi][ni], a_hi[mi], &b[ni >> 1][(ni & 1) * 2]);
            }
        }
    }

    // ---- epilogue ----
#pragma unroll
    for (int mi = 0; mi < 2; mi++) {
#pragma unroll
        for (int ni = 0; ni < 8; ni++) {
            int cc = n0 + wn * 64 + ni * 8 + (lane & 3) * 2;
#pragma unroll
            for (int hh = 0; hh < 2; hh++) {
                int m = m0 + wm * 32 + mi * 16 + (lane >> 2) + hh * 8;
                if (m >= M) continue;
                float v0 = acc[mi][ni][hh * 2 + 0];
                float v1 = acc[mi][ni][hh * 2 + 1];
                if (BIAS) { v0 += bias[cc]; v1 += bias[cc + 1]; }
                if (ACT == 1) { v0 = gelu_fast(v0); v1 = gelu_fast(v1); }
                if (RES) {
                    const float* rp = res + (size_t)m * ldr + cc;
                    v0 += rp[0]; v1 += rp[1];
                }
                if (OHALF) {
                    *(uint32_t*)(Cf + (size_t)m * ldc + cc) =
                        pk2(__float2half_rn(v0), __float2half_rn(v1));
                } else {
                    *(float2*)(C + (size_t)m * ldc + cc) = make_float2(v0, v1);
                }
            }
        }
    }
}

// ---------------- CSR build ----------------
__global__ void zero_counts() {
    int i = blockIdx.x * blockDim.x + threadIdx.x;
    if (i < NS) g_counts[i] = 0;
}
__global__ void hist_kernel(const int* __restrict__ edge_dst) {
    int i = blockIdx.x * blockDim.x + threadIdx.x;
    if (i < EDG) atomicAdd(&g_counts[edge_dst[i]], 1);
}
__global__ void __launch_bounds__(SCAN_B) scan_pass1() {
    __shared__ int ws[32];
    int b = blockIdx.x, t = threadIdx.x;
    int i = b * SCAN_B + t;
    int v = (i < NS) ? g_counts[i] : 0;
#pragma unroll
    for (int o = 16; o; o >>= 1) v += __shfl_xor_sync(0xFFFFFFFFu, v, o);
    if ((t & 31) == 0) ws[t >> 5] = v;
    __syncthreads();
    if (t < 32) {
        int x = ws[t];
#pragma unroll
        for (int o = 16; o; o >>= 1) x += __shfl_xor_sync(0xFFFFFFFFu, x, o);
        if (t == 0) g_bsum[b] = x;
    }
}
__global__ void scan_pass2() {
    __shared__ int sh[128];
    int t = threadIdx.x;
    int orig = (t < NBLK) ? g_bsum[t] : 0;
    sh[t] = orig;
    __syncthreads();
    for (int o = 1; o < 128; o <<= 1) {
        int v = (t >= o) ? sh[t - o] : 0;
        __syncthreads();
        sh[t] += v;
        __syncthreads();
    }
    if (t < NBLK) g_bsum[t] = sh[t] - orig;
}
__global__ void __launch_bounds__(SCAN_B) scan_pass3() {
    __shared__ int ws[32];
    int b = blockIdx.x, t = threadIdx.x;
    int lane = t & 31, w = t >> 5;
    int i = b * SCAN_B + t;
    int v = (i < NS) ? g_counts[i] : 0;
    int x = v;
#pragma unroll
    for (int o = 1; o < 32; o <<= 1) {
        int y = __shfl_up_sync(0xFFFFFFFFu, x, o);
        if (lane >= o) x += y;
    }
    if (lane == 31) ws[w] = x;
    __syncthreads();
    if (w == 0) {
        int sv = ws[lane];
#pragma unroll
        for (int o = 1; o < 32; o <<= 1) {
            int y = __shfl_up_sync(0xFFFFFFFFu, sv, o);
            if (lane >= o) sv += y;
        }
        ws[lane] = sv;
    }
    __syncthreads();
    int incl = x + (w > 0 ? ws[w - 1] : 0) + g_bsum[b];
    if (i < NS) {
        g_offsets[i + 1] = incl;
        g_cursor[i] = incl - v;
    }
    if (b == 0 && t == 0) g_offsets[0] = 0;
}
__global__ void scatter_kernel(const int* __restrict__ edge_src,
                               const int* __restrict__ edge_dst) {
    int i = blockIdx.x * blockDim.x + threadIdx.x;
    if (i >= EDG) return;
    int dst = edge_dst[i];
    int pos = atomicAdd(&g_cursor[dst], 1);
    g_csr_src[pos] = edge_src[i];
}

// ---------------- attention: warp per dst, lane = (head, quarter) ----------------
__global__ void __launch_bounds__(256) attn_kernel() {
    int gw = (blockIdx.x * blockDim.x + threadIdx.x) >> 5;
    if (gw >= NS) return;
    int lane = threadIdx.x & 31;
    int off = (lane >> 2) * 32 + (lane & 3) * 8;

    int beg = g_offsets[gw];
    int end = g_offsets[gw + 1];

    const float* dfp = g_df + (size_t)gw * 256 + off;
    float4 d0 = *(const float4*)(dfp);
    float4 d1 = *(const float4*)(dfp + 4);

    float m = -1e30f, den = 0.0f;
    float4 a0 = make_float4(0.f, 0.f, 0.f, 0.f);
    float4 a1 = make_float4(0.f, 0.f, 0.f, 0.f);

    int e = beg;
    for (; e + 2 <= end; e += 2) {
        int s0 = __ldg(&g_csr_src[e]);
        int s1 = __ldg(&g_csr_src[e + 1]);
        uint4 rx = __ldg((const uint4*)(g_zf + (size_t)s0 * 256 + off));
        uint4 ry = __ldg((const uint4*)(g_zf + (size_t)s1 * 256 + off));
        const __half2* hx = (const __half2*)&rx;
        const __half2* hy = (const __half2*)&ry;
        float2 xa = __half22float2(hx[0]), xb = __half22float2(hx[1]);
        float2 xc = __half22float2(hx[2]), xd = __half22float2(hx[3]);
        float2 ya = __half22float2(hy[0]), yb = __half22float2(hy[1]);
        float2 yc = __half22float2(hy[2]), yd = __half22float2(hy[3]);
        float4 x0 = make_float4(xa.x, xa.y, xb.x, xb.y);
        float4 x1 = make_float4(xc.x, xc.y, xd.x, xd.y);
        float4 y0 = make_float4(ya.x, ya.y, yb.x, yb.y);
        float4 y1 = make_float4(yc.x, yc.y, yd.x, yd.y);

        float sa = x0.x * d0.x + x0.y * d0.y + x0.z * d0.z + x0.w * d0.w
                 + x1.x * d1.x + x1.y * d1.y + x1.z * d1.z + x1.w * d1.w;
        float sb = y0.x * d0.x + y0.y * d0.y + y0.z * d0.z + y0.w * d0.w
                 + y1.x * d1.x + y1.y * d1.y + y1.z * d1.z + y1.w * d1.w;
        sa += __shfl_xor_sync(0xFFFFFFFFu, sa, 1);
        sb += __shfl_xor_sync(0xFFFFFFFFu, sb, 1);
        sa += __shfl_xor_sync(0xFFFFFFFFu, sa, 2);
        sb += __shfl_xor_sync(0xFFFFFFFFu, sb, 2);

        {
            float mn = fmaxf(m, sa);
            float sc = __expf(m - mn);
            float w  = __expf(sa - mn);
            den = den * sc + w;
            a0.x = a0.x * sc + w * x0.x; a0.y = a0.y * sc + w * x0.y;
            a0.z = a0.z * sc + w * x0.z; a0.w = a0.w * sc + w * x0.w;
            a1.x = a1.x * sc + w * x1.x; a1.y = a1.y * sc + w * x1.y;
            a1.z = a1.z * sc + w * x1.z; a1.w = a1.w * sc + w * x1.w;
            m = mn;
        }
        {
            float mn = fmaxf(m, sb);
            float sc = __expf(m - mn);
            float w  = __expf(sb - mn);
            den = den * sc + w;
            a0.x = a0.x * sc + w * y0.x; a0.y = a0.y * sc + w * y0.y;
            a0.z = a0.z * sc + w * y0.z; a0.w = a0.w * sc + w * y0.w;
            a1.x = a1.x * sc + w * y1.x; a1.y = a1.y * sc + w * y1.y;
            a1.z = a1.z * sc + w * y1.z; a1.w = a1.w * sc + w * y1.w;
            m = mn;
        }
    }
    for (; e < end; e++) {
        int s0 = __ldg(&g_csr_src[e]);
        uint4 rx = __ldg((const uint4*)(g_zf + (size_t)s0 * 256 + off));
        const __half2* hx = (const __half2*)&rx;
        float2 xa = __half22float2(hx[0]), xb = __half22float2(hx[1]);
        float2 xc = __half22float2(hx[2]), xd = __half22float2(hx[3]);
        float4 x0 = make_float4(xa.x, xa.y, xb.x, xb.y);
        float4 x1 = make_float4(xc.x, xc.y, xd.x, xd.y);
        float sa = x0.x * d0.x + x0.y * d0.y + x0.z * d0.z + x0.w * d0.w
                 + x1.x * d1.x + x1.y * d1.y + x1.z * d1.z + x1.w * d1.w;
        sa += __shfl_xor_sync(0xFFFFFFFFu, sa, 1);
        sa += __shfl_xor_sync(0xFFFFFFFFu, sa, 2);
        float mn = fmaxf(m, sa);
        float sc = __expf(m - mn);
        float w  = __expf(sa - mn);
        den = den * sc + w;
        a0.x = a0.x * sc + w * x0.x; a0.y = a0.y * sc + w * x0.y;
        a0.z = a0.z * sc + w * x0.z; a0.w = a0.w * sc + w * x0.w;
        a1.x = a1.x * sc + w * x1.x; a1.y = a1.y * sc + w * x1.y;
        a1.z = a1.z * sc + w * x1.z; a1.w = a1.w * sc + w * x1.w;
        m = mn;
    }

    float inv = 1.0f / den;
    float v[8];
    v[0] = a0.x * inv; v[1] = a0.y * inv; v[2] = a0.z * inv; v[3] = a0.w * inv;
    v[4] = a1.x * inv; v[5] = a1.y * inv; v[6] = a1.z * inv; v[7] = a1.w * inv;
    f16 hv[8];
#pragma unroll
    for (int i = 0; i < 8; i++) {
        v[i] = (v[i] > 0.0f) ? v[i] : expm1f(v[i]);  // ELU(alpha=1)
        hv[i] = __float2half_rn(v[i]);
    }
    size_t ob = (size_t)gw * 256 + off;
    *(uint4*)(g_hf + ob) = make_uint4(pk2(hv[0], hv[1]), pk2(hv[2], hv[3]),
                                      pk2(hv[4], hv[5]), pk2(hv[6], hv[7]));
}

// ---------------- layernorm: warp per row, lane owns 8 contiguous cols ----------------
__global__ void ln_kernel(const float* __restrict__ x,
                          const float* __restrict__ gam,
                          const float* __restrict__ bet) {
    int row = (blockIdx.x * blockDim.x + threadIdx.x) >> 5;
    if (row >= NS) return;
    int lane = threadIdx.x & 31;
    const float* xp = x + (size_t)row * 256 + lane * 8;
    float4 va = *(const float4*)xp;
    float4 vb = *(const float4*)(xp + 4);
    float v[8] = {va.x, va.y, va.z, va.w, vb.x, vb.y, vb.z, vb.w};
    float s = 0.0f, s2 = 0.0f;
#pragma unroll
    for (int r = 0; r < 8; r++) { s += v[r]; s2 += v[r] * v[r]; }
#pragma unroll
    for (int o = 16; o > 0; o >>= 1) {
        s  += __shfl_xor_sync(0xFFFFFFFFu, s, o);
        s2 += __shfl_xor_sync(0xFFFFFFFFu, s2, o);
    }
    float mean = s * (1.0f / 256.0f);
    float var = s2 * (1.0f / 256.0f) - mean * mean;
    float inv = rsqrtf(var + 1e-6f);
    float4 ga = *(const float4*)(gam + lane * 8);
    float4 gb = *(const float4*)(gam + lane * 8 + 4);
    float4 ba = *(const float4*)(bet + lane * 8);
    float4 bb = *(const float4*)(bet + lane * 8 + 4);
    float g[8] = {ga.x, ga.y, ga.z, ga.w, gb.x, gb.y, gb.z, gb.w};
    float bt[8] = {ba.x, ba.y, ba.z, ba.w, bb.x, bb.y, bb.z, bb.w};
    f16 hv[8];
#pragma unroll
    for (int r = 0; r < 8; r++) {
        float y = (v[r] - mean) * inv * g[r] + bt[r];
        hv[r] = __float2half_rn(y);
    }
    size_t ob = (size_t)row * 256 + lane * 8;
    *(uint4*)(g_xnf + ob) = make_uint4(pk2(hv[0], hv[1]), pk2(hv[2], hv[3]),
                                       pk2(hv[4], hv[5]), pk2(hv[6], hv[7]));
}

// ---------------- launch ----------------
extern "C" void kernel_launch(void* const* d_in, const int* in_sizes, int n_in,
                              void* d_out, int out_size) {
    const float* s_in      = (const float*)d_in[0];
    const float* e_in      = (const float*)d_in[1];
    const float* dst_feat  = (const float*)d_in[2];
    const float* fc_w      = (const float*)d_in[3];
    const float* dstfeat_w = (const float*)d_in[4];
    const float* proj_w    = (const float*)d_in[5];
    const float* proj_b    = (const float*)d_in[6];
    const float* ln_g      = (const float*)d_in[7];
    const float* ln_b      = (const float*)d_in[8];
    const float* w1        = (const float*)d_in[9];
    const float* b1        = (const float*)d_in[10];
    const float* w2        = (const float*)d_in[11];
    const float* b2        = (const float*)d_in[12];
    const int*   edge_src  = (const int*)d_in[13];
    const int*   edge_dst  = (const int*)d_in[14];
    float* out = (float*)d_out;

    float *dfp, *xp, *xsp;
    cudaGetSymbolAddress((void**)&dfp, g_df);
    cudaGetSymbolAddress((void**)&xp,  g_x);
    cudaGetSymbolAddress((void**)&xsp, g_xs);
    bf16 *eh, *el, *wzh, *wzl;
    cudaGetSymbolAddress((void**)&eh,  g_eh);  cudaGetSymbolAddress((void**)&el,  g_el);
    cudaGetSymbolAddress((void**)&wzh, g_wzh); cudaGetSymbolAddress((void**)&wzl, g_wzl);
    f16 *zf, *ff, *wd16, *sf, *hf, *xnf, *tf, *pw, *w1p, *w2p;
    cudaGetSymbolAddress((void**)&zf,   g_zf);
    cudaGetSymbolAddress((void**)&ff,   g_ff);
    cudaGetSymbolAddress((void**)&wd16, g_wd16);
    cudaGetSymbolAddress((void**)&sf,   g_sf);
    cudaGetSymbolAddress((void**)&hf,   g_hf);
    cudaGetSymbolAddress((void**)&xnf,  g_xnf);
    cudaGetSymbolAddress((void**)&tf,   g_tf);
    cudaGetSymbolAddress((void**)&pw,   g_pw);
    cudaGetSymbolAddress((void**)&w1p,  g_w1);
    cudaGetSymbolAddress((void**)&w2p,  g_w2);

    cudaFuncSetAttribute(mma_gemm<bf16, 3, 2, 0, false, false, true>,
                         cudaFuncAttributeMaxDynamicSharedMemorySize, SMEM_BF3);
    cudaFuncSetAttribute(mma_gemm<f16, 1, 3, 0, false, false, false>,
                         cudaFuncAttributeMaxDynamicSharedMemorySize, SMEM_FP1);
    cudaFuncSetAttribute(mma_gemm<f16, 1, 3, 0, true, false, false>,
                         cudaFuncAttributeMaxDynamicSharedMemorySize, SMEM_FP1);
    cudaFuncSetAttribute(mma_gemm<f16, 1, 3, 0, false, true, false>,
                         cudaFuncAttributeMaxDynamicSharedMemorySize, SMEM_FP1);
    cudaFuncSetAttribute(mma_gemm<f16, 1, 3, 1, true, false, true>,
                         cudaFuncAttributeMaxDynamicSharedMemorySize, SMEM_FP1);
    cudaFuncSetAttribute(mma_gemm<f16, 1, 3, 0, true, true, false>,
                         cudaFuncAttributeMaxDynamicSharedMemorySize, SMEM_FP1);

    const int TB = 256;
    const int MB = (NS + 127) / 128;  // 782

    // ---- side stream for the independent CSR + conversion + xs chain ----
    cudaStream_t s1;
    cudaStreamCreateWithFlags(&s1, cudaStreamNonBlocking);
    cudaEvent_t evFork, evJoin;
    cudaEventCreateWithFlags(&evFork, cudaEventDisableTiming);
    cudaEventCreateWithFlags(&evJoin, cudaEventDisableTiming);

    cudaEventRecord(evFork, 0);
    cudaStreamWaitEvent(s1, evFork, 0);

    // ---- main stream: conversions needed by z/df, then the two pre-softmax GEMMs ----
    act_split_bf<<<(NE * D / 4 + TB - 1) / TB, TB>>>(e_in, eh, el, NE * D);       // 0
    repack_split<<<(256 * 256 + TB - 1) / TB, TB>>>(fc_w, wzh, wzl, 256);         // 1
    act_rn16<<<(NS * FEAT / 4 + TB - 1) / TB, TB>>>(dst_feat, ff, NS * FEAT);     // 2
    // 3: z = e @ Wz  [NE,256] -> fp16 (bf16 3-pass, 2-stage) — ncu capture slot
    mma_gemm<bf16, 3, 2, 0, false, false, true><<<dim3(2, MB), TB, SMEM_BF3>>>(
        eh, el, 256, eh, el, 256, D, wzh, wzl, 256,
        nullptr, nullptr, 0, nullptr, zf, 256, NE, 256);
    repack_rn16<<<(64 * 256 + TB - 1) / TB, TB>>>(dstfeat_w, wd16, 64);           // 4
    // 5: df = dst_feat @ Wd  [NS,256] (fp32 out; fp16 1-pass, 2 k-tiles)
    mma_gemm<f16, 1, 3, 0, false, false, false><<<dim3(2, MB), TB, SMEM_FP1>>>(
        ff, nullptr, 64, ff, nullptr, 64, FEAT, wd16, nullptr, 64,
        nullptr, nullptr, 0, dfp, nullptr, 256, NS, 64);

    // ---- side stream: CSR + conversions + xs = s @ proj_w[256:] + b ----
    zero_counts<<<(NS + TB - 1) / TB, TB, 0, s1>>>();
    hist_kernel<<<(EDG + TB - 1) / TB, TB, 0, s1>>>(edge_dst);
    scan_pass1<<<NBLK, SCAN_B, 0, s1>>>();
    scan_pass2<<<1, 128, 0, s1>>>();
    scan_pass3<<<NBLK, SCAN_B, 0, s1>>>();
    scatter_kernel<<<(EDG + TB - 1) / TB, TB, 0, s1>>>(edge_src, edge_dst);
    act_rn16<<<(NS * D / 4 + TB - 1) / TB, TB, 0, s1>>>(s_in, sf, NS * D);
    wsplit_t16<<<(512 * 256 + TB - 1) / TB, TB, 0, s1>>>(proj_w, pw, 512, 256);
    wsplit_t16<<<(256 * 512 + TB - 1) / TB, TB, 0, s1>>>(w1, w1p, 256, 512);
    wsplit_t16<<<(512 * 256 + TB - 1) / TB, TB, 0, s1>>>(w2, w2p, 512, 256);
    // xs: uses B rows' k in [256, 512) via pointer offset (ldbk = 512)
    mma_gemm<f16, 1, 3, 0, true, false, false><<<dim3(2, MB), TB, SMEM_FP1, s1>>>(
        sf, nullptr, 256, sf, nullptr, 256, 256, pw + 256, nullptr, 512,
        proj_b, nullptr, 0, xsp, nullptr, 256, NS, 256);
    cudaEventRecord(evJoin, s1);

    cudaStreamWaitEvent(0, evJoin, 0);

    // attention + ELU -> h fp16 rn
    attn_kernel<<<(NS * 32 + TB - 1) / TB, TB>>>();

    // proj (h-half only): h @ proj_w[:256] + xs -> g_x (fp32)
    mma_gemm<f16, 1, 3, 0, false, true, false><<<dim3(2, MB), TB, SMEM_FP1>>>(
        hf, nullptr, 256, hf, nullptr, 256, 256, pw, nullptr, 512,
        nullptr, xsp, 256, xp, nullptr, 256, NS, 256);

    // layernorm -> xn fp16 rn
    ln_kernel<<<(NS * 32 + TB - 1) / TB, TB>>>(xp, ln_g, ln_b);

    // ffn1: gelu(xn @ w1 + b1) -> t fp16 rn
    mma_gemm<f16, 1, 3, 1, true, false, true><<<dim3(4, MB), TB, SMEM_FP1>>>(
        xnf, nullptr, 256, xnf, nullptr, 256, 256, w1p, nullptr, 256,
        b1, nullptr, 0, nullptr, tf, 512, NS, 256);

    // ffn2: t @ w2 + b2 + g_x -> out (fp32)
    mma_gemm<f16, 1, 3, 0, true, true, false><<<dim3(2, MB), TB, SMEM_FP1>>>(
        tf, nullptr, 512, tf, nullptr, 512, 512, w2p, nullptr, 512,
        b2, xp, 256, out, nullptr, 256, NS, 512);
}

// round 16
// speedup vs baseline: 1.0540x; 1.0540x over previous
#include <cuda_runtime.h>
#include <cuda_bf16.h>
#include <cuda_fp16.h>
#include <cstdint>
#include <math.h>

// Problem constants (fixed by the dataset)
#define NS 100000
#define NE 100000
#define EDG 1600000
#define D 256
#define H 8
#define HD 32
#define FEAT 64
#define DFF 512

#define SCAN_B 1024
#define NBLK ((NS + SCAN_B - 1) / SCAN_B)   // 98

// smem tile geometry: 32 elems of k per row, padded to 40 (80 B)
#define KP 40
#define ROWB 80
#define MATB (128 * ROWB)          // 10240 B per matrix
#define SMEM_BF3 (2 * 4 * MATB)    // 81920 B: bf16 3-pass, 2 stages (Ah,Al,Bh,Bl)
#define SMEM_FP1 (3 * 2 * MATB)    // 61440 B: fp16 1-pass, 3 stages (A,B)

typedef __nv_bfloat16 bf16;
typedef __half f16;

// ---------------- device scratch (no allocations allowed) ----------------
__device__ f16   g_zf[(size_t)NE * D];   // z in fp16 (gathered by attention)
__device__ float g_df[(size_t)NS * D];
__device__ float g_x[(size_t)NS * D];
// bf16 split (z path)
__device__ bf16 g_eh[(size_t)NE * D], g_el[(size_t)NE * D];
__device__ bf16 g_wzh[256 * 256], g_wzl[256 * 256];
// fp16 rn
__device__ f16 g_ff[(size_t)NS * FEAT];  // dst_feat fp16
__device__ f16 g_wd16[256 * 64];         // dstfeat_w transposed fp16
__device__ f16 g_sf[(size_t)NS * D];
__device__ f16 g_hf[(size_t)NS * D];
__device__ f16 g_xnf[(size_t)NS * D];
__device__ f16 g_tf[(size_t)NS * DFF];
// fp16 plain transposed weights Wt[n][k]
__device__ f16 g_pw[256 * 512];
__device__ f16 g_w1[512 * 256];
__device__ f16 g_w2[256 * 512];
// CSR
__device__ int g_counts[NS];
__device__ int g_offsets[NS + 1];
__device__ int g_cursor[NS];
__device__ int g_csr_src[EDG];
__device__ int g_bsum[NBLK];

// ---------------- small helpers ----------------
__device__ __forceinline__ float gelu_fast(float x) {
    const float c = 0.7978845608028654f;
    float u = c * (x + 0.044715f * x * x * x);
    float e = __expf(2.0f * u);
    float th = 1.0f - 2.0f / (e + 1.0f);
    return 0.5f * x * (1.0f + th);
}
__device__ __forceinline__ uint32_t smem_u32(const void* p) {
    uint32_t a;
    asm("{ .reg .u64 t; cvta.to.shared.u64 t, %1; cvt.u32.u64 %0, t; }" : "=r"(a) : "l"(p));
    return a;
}
__device__ __forceinline__ void ldm_x4(uint32_t* r, uint32_t addr) {
    asm volatile("ldmatrix.sync.aligned.m8n8.x4.shared.b16 {%0,%1,%2,%3}, [%4];"
                 : "=r"(r[0]), "=r"(r[1]), "=r"(r[2]), "=r"(r[3]) : "r"(addr));
}
__device__ __forceinline__ uint32_t pk2(bf16 a, bf16 b) {
    __nv_bfloat162 t(a, b); return *(uint32_t*)&t;
}
__device__ __forceinline__ uint32_t pk2(f16 a, f16 b) {
    __half2 t(a, b); return *(uint32_t*)&t;
}
__device__ __forceinline__ void split2(float x, bf16& hi, bf16& lo) {
    hi = __float2bfloat16_rn(x);
    lo = __float2bfloat16_rn(x - __bfloat162float(hi));
}
template <typename T>
__device__ __forceinline__ void mma_t(float* c, const uint32_t* a, const uint32_t* b);
template <>
__device__ __forceinline__ void mma_t<bf16>(float* c, const uint32_t* a, const uint32_t* b) {
    asm volatile(
        "mma.sync.aligned.m16n8k16.row.col.f32.bf16.bf16.f32 "
        "{%0,%1,%2,%3}, {%4,%5,%6,%7}, {%8,%9}, {%0,%1,%2,%3};"
        : "+f"(c[0]), "+f"(c[1]), "+f"(c[2]), "+f"(c[3])
        : "r"(a[0]), "r"(a[1]), "r"(a[2]), "r"(a[3]), "r"(b[0]), "r"(b[1]));
}
template <>
__device__ __forceinline__ void mma_t<f16>(float* c, const uint32_t* a, const uint32_t* b) {
    asm volatile(
        "mma.sync.aligned.m16n8k16.row.col.f32.f16.f16.f32 "
        "{%0,%1,%2,%3}, {%4,%5,%6,%7}, {%8,%9}, {%0,%1,%2,%3};"
        : "+f"(c[0]), "+f"(c[1]), "+f"(c[2]), "+f"(c[3])
        : "r"(a[0]), "r"(a[1]), "r"(a[2]), "r"(a[3]), "r"(b[0]), "r"(b[1]));
}
__device__ __forceinline__ void cpa16(uint32_t dst, const void* src, bool pred) {
    int sz = pred ? 16 : 0;
    asm volatile("cp.async.cg.shared.global [%0], [%1], 16, %2;"
                 :: "r"(dst), "l"(src), "r"(sz) : "memory");
}

// ---------------- conversion kernels ----------------
__global__ void act_split_bf(const float* __restrict__ in, bf16* __restrict__ hi,
                             bf16* __restrict__ lo, int n) {
    int i = 4 * (blockIdx.x * blockDim.x + threadIdx.x);
    if (i >= n) return;
    float4 v = *(const float4*)(in + i);
    bf16 h0, l0, h1, l1, h2, l2, h3, l3;
    split2(v.x, h0, l0); split2(v.y, h1, l1);
    split2(v.z, h2, l2); split2(v.w, h3, l3);
    *(uint2*)(hi + i) = make_uint2(pk2(h0, h1), pk2(h2, h3));
    *(uint2*)(lo + i) = make_uint2(pk2(l0, l1), pk2(l2, l3));
}
__global__ void act_rn16(const float* __restrict__ in, f16* __restrict__ o, int n) {
    int i = 4 * (blockIdx.x * blockDim.x + threadIdx.x);
    if (i >= n) return;
    float4 v = *(const float4*)(in + i);
    *(uint2*)(o + i) = make_uint2(pk2(__float2half_rn(v.x), __float2half_rn(v.y)),
                                  pk2(__float2half_rn(v.z), __float2half_rn(v.w)));
}
__global__ void wsplit_t16(const float* __restrict__ w, f16* __restrict__ o, int K, int N) {
    int idx = blockIdx.x * blockDim.x + threadIdx.x;
    if (idx >= K * N) return;
    int k = idx / N, n = idx % N;
    o[(size_t)n * K + k] = __float2half_rn(w[idx]);
}
// per-head weight (H, K, HD) -> bf16 split Wt[256][K]
__global__ void repack_split(const float* __restrict__ w, bf16* __restrict__ hi,
                             bf16* __restrict__ lo, int K) {
    int idx = blockIdx.x * blockDim.x + threadIdx.x;
    if (idx >= K * 256) return;
    int n = idx / K, k = idx % K;
    bf16 h, l;
    split2(w[(n >> 5) * (K * 32) + k * 32 + (n & 31)], h, l);
    hi[idx] = h;
    lo[idx] = l;
}
// per-head weight (H, K, HD) -> fp16 rn Wt[256][K]
__global__ void repack_rn16(const float* __restrict__ w, f16* __restrict__ o, int K) {
    int idx = blockIdx.x * blockDim.x + threadIdx.x;
    if (idx >= K * 256) return;
    int n = idx / K, k = idx % K;
    o[idx] = __float2half_rn(w[(n >> 5) * (K * 32) + k * 32 + (n & 31)]);
}

// ================= multistage cp.async GEMM =================
// PASSES==3 (bf16): Ah*Bh + Al*Bh + Ah*Bl.  PASSES==1 (fp16): A*B plain rn.
template <typename T, int PASSES, int NSTAGE, int ACT, bool BIAS, bool RES, bool OHALF>
__global__ void __launch_bounds__(256, 2) mma_gemm(
    const T* __restrict__ Ah0, const T* __restrict__ Al0, int lda0,
    const T* __restrict__ Ah1, const T* __restrict__ Al1, int lda1, int ksplit,
    const T* __restrict__ Bh, const T* __restrict__ Bl, int ldbk,
    const float* __restrict__ bias,
    const float* __restrict__ res, int ldr,
    float* __restrict__ C, f16* __restrict__ Cf, int ldc,
    int M, int K)
{
    constexpr int NMAT = (PASSES == 3) ? 4 : 2;
    constexpr int STB = NMAT * MATB;
    constexpr int BOFF = (PASSES == 3) ? 2 * MATB : MATB;
    extern __shared__ char dsm[];
    uint32_t sb = smem_u32(dsm);

    int t = threadIdx.x;
    int lane = t & 31, wid = t >> 5;
    int m0 = blockIdx.y * 128;
    int n0 = blockIdx.x * 128;
    int wm = wid & 3;
    int wn = wid >> 2;

    float acc[2][8][4];
#pragma unroll
    for (int i = 0; i < 2; i++)
#pragma unroll
        for (int j = 0; j < 8; j++)
#pragma unroll
            for (int q = 0; q < 4; q++) acc[i][j][q] = 0.0f;

    uint32_t a_off = (uint32_t)(((wm * 32 + (lane & 15)) * KP + (lane >> 4) * 8) * 2);
    uint32_t b_off = (uint32_t)(((wn * 64 + (lane & 7) + (lane >> 4) * 8) * KP
                                 + ((lane >> 3) & 1) * 8) * 2);

    int p_row = t >> 1;
    int p_c0 = (t & 1) * 2;
    bool a_ok = (m0 + p_row) < M;
    const int KT = K >> 5;

    auto prefetch = [&](int kt) {
        if (kt < KT) {
            int k0 = kt * 32;
            int stage = kt % NSTAGE;
            const T *AhS, *AlS; int lda, koff;
            if (k0 < ksplit) { AhS = Ah0; AlS = Al0; lda = lda0; koff = k0; }
            else             { AhS = Ah1; AlS = Al1; lda = lda1; koff = k0 - ksplit; }
            const T* pah = AhS + (size_t)(m0 + p_row) * lda + koff;
            const T* pbh = Bh + (size_t)(n0 + p_row) * ldbk + k0;
            uint32_t base = sb + stage * STB + p_row * ROWB;
#pragma unroll
            for (int ci = 0; ci < 2; ci++) {
                int c = p_c0 + ci;
                cpa16(base + c * 16,        pah + c * 8, a_ok);
                cpa16(base + BOFF + c * 16, pbh + c * 8, true);
                if (PASSES == 3) {
                    const T* pal = AlS + (size_t)(m0 + p_row) * lda + koff;
                    const T* pbl = Bl + (size_t)(n0 + p_row) * ldbk + k0;
                    cpa16(base + MATB + c * 16,     pal + c * 8, a_ok);
                    cpa16(base + 3 * MATB + c * 16, pbl + c * 8, true);
                }
            }
        }
        asm volatile("cp.async.commit_group;" ::: "memory");
    };

#pragma unroll
    for (int s = 0; s < NSTAGE - 1; s++) prefetch(s);

    for (int kt = 0; kt < KT; kt++) {
        if (NSTAGE == 2) asm volatile("cp.async.wait_group 0;" ::: "memory");
        else             asm volatile("cp.async.wait_group 1;" ::: "memory");
        __syncthreads();

        prefetch(kt + NSTAGE - 1);

        uint32_t s0 = sb + (kt % NSTAGE) * STB;
        uint32_t sAh = s0, sBh = s0 + BOFF;

#pragma unroll
        for (int ks = 0; ks < 2; ks++) {
            uint32_t koffb = (uint32_t)(ks * 32);
            uint32_t a_hi[2][4], b[4][4];
            ldm_x4(a_hi[0], sAh + a_off + koffb);
            ldm_x4(a_hi[1], sAh + a_off + koffb + 16 * KP * 2);
#pragma unroll
            for (int ni2 = 0; ni2 < 4; ni2++)
                ldm_x4(b[ni2], sBh + b_off + koffb + ni2 * 16 * KP * 2);
            // pass 1: Ah * Bh
#pragma unroll
            for (int mi = 0; mi < 2; mi++)
#pragma unroll
                for (int ni = 0; ni < 8; ni++)
                    mma_t<T>(acc[mi][ni], a_hi[mi], &b[ni >> 1][(ni & 1) * 2]);
            if (PASSES == 3) {
                uint32_t sAl = s0 + MATB, sBl = s0 + 3 * MATB;
                uint32_t a_lo[2][4];
                ldm_x4(a_lo[0], sAl + a_off + koffb);
                ldm_x4(a_lo[1], sAl + a_off + koffb + 16 * KP * 2);
#pragma unroll
                for (int mi = 0; mi < 2; mi++)
#pragma unroll
                    for (int ni = 0; ni < 8; ni++)
                        mma_t<T>(acc[mi][ni], a_lo[mi], &b[ni >> 1][(ni & 1) * 2]);
#pragma unroll
                for (int ni2 = 0; ni2 < 4; ni2++)
                    ldm_x4(b[ni2], sBl + b_off + koffb + ni2 * 16 * KP * 2);
#pragma unroll
                for (int mi = 0; mi < 2; mi++)
#pragma unroll
                    for (int ni = 0; ni < 8; ni++)
                        mma_t<T>(acc[mi][ni], a_hi[mi], &b[ni >> 1][(ni & 1) * 2]);
            }
        }
    }

    // ---- epilogue ----
#pragma unroll
    for (int mi = 0; mi < 2; mi++) {
#pragma unroll
        for (int ni = 0; ni < 8; ni++) {
            int cc = n0 + wn * 64 + ni * 8 + (lane & 3) * 2;
#pragma unroll
            for (int hh = 0; hh < 2; hh++) {
                int m = m0 + wm * 32 + mi * 16 + (lane >> 2) + hh * 8;
                if (m >= M) continue;
                float v0 = acc[mi][ni][hh * 2 + 0];
                float v1 = acc[mi][ni][hh * 2 + 1];
                if (BIAS) { v0 += bias[cc]; v1 += bias[cc + 1]; }
                if (ACT == 1) { v0 = gelu_fast(v0); v1 = gelu_fast(v1); }
                if (RES) {
                    const float* rp = res + (size_t)m * ldr + cc;
                    v0 += rp[0]; v1 += rp[1];
                }
                if (OHALF) {
                    *(uint32_t*)(Cf + (size_t)m * ldc + cc) =
                        pk2(__float2half_rn(v0), __float2half_rn(v1));
                } else {
                    *(float2*)(C + (size_t)m * ldc + cc) = make_float2(v0, v1);
                }
            }
        }
    }
}

// ---------------- CSR build ----------------
__global__ void zero_counts() {
    int i = blockIdx.x * blockDim.x + threadIdx.x;
    if (i < NS) g_counts[i] = 0;
}
__global__ void hist_kernel(const int* __restrict__ edge_dst) {
    int i = blockIdx.x * blockDim.x + threadIdx.x;
    if (i < EDG) atomicAdd(&g_counts[edge_dst[i]], 1);
}
__global__ void __launch_bounds__(SCAN_B) scan_pass1() {
    __shared__ int ws[32];
    int b = blockIdx.x, t = threadIdx.x;
    int i = b * SCAN_B + t;
    int v = (i < NS) ? g_counts[i] : 0;
#pragma unroll
    for (int o = 16; o; o >>= 1) v += __shfl_xor_sync(0xFFFFFFFFu, v, o);
    if ((t & 31) == 0) ws[t >> 5] = v;
    __syncthreads();
    if (t < 32) {
        int x = ws[t];
#pragma unroll
        for (int o = 16; o; o >>= 1) x += __shfl_xor_sync(0xFFFFFFFFu, x, o);
        if (t == 0) g_bsum[b] = x;
    }
}
__global__ void scan_pass2() {
    __shared__ int sh[128];
    int t = threadIdx.x;
    int orig = (t < NBLK) ? g_bsum[t] : 0;
    sh[t] = orig;
    __syncthreads();
    for (int o = 1; o < 128; o <<= 1) {
        int v = (t >= o) ? sh[t - o] : 0;
        __syncthreads();
        sh[t] += v;
        __syncthreads();
    }
    if (t < NBLK) g_bsum[t] = sh[t] - orig;
}
__global__ void __launch_bounds__(SCAN_B) scan_pass3() {
    __shared__ int ws[32];
    int b = blockIdx.x, t = threadIdx.x;
    int lane = t & 31, w = t >> 5;
    int i = b * SCAN_B + t;
    int v = (i < NS) ? g_counts[i] : 0;
    int x = v;
#pragma unroll
    for (int o = 1; o < 32; o <<= 1) {
        int y = __shfl_up_sync(0xFFFFFFFFu, x, o);
        if (lane >= o) x += y;
    }
    if (lane == 31) ws[w] = x;
    __syncthreads();
    if (w == 0) {
        int sv = ws[lane];
#pragma unroll
        for (int o = 1; o < 32; o <<= 1) {
            int y = __shfl_up_sync(0xFFFFFFFFu, sv, o);
            if (lane >= o) sv += y;
        }
        ws[lane] = sv;
    }
    __syncthreads();
    int incl = x + (w > 0 ? ws[w - 1] : 0) + g_bsum[b];
    if (i < NS) {
        g_offsets[i + 1] = incl;
        g_cursor[i] = incl - v;
    }
    if (b == 0 && t == 0) g_offsets[0] = 0;
}
__global__ void scatter_kernel(const int* __restrict__ edge_src,
                               const int* __restrict__ edge_dst) {
    int i = blockIdx.x * blockDim.x + threadIdx.x;
    if (i >= EDG) return;
    int dst = edge_dst[i];
    int pos = atomicAdd(&g_cursor[dst], 1);
    g_csr_src[pos] = edge_src[i];
}

// ---------------- attention: warp per dst, lane = (head, quarter) ----------------
__global__ void __launch_bounds__(256) attn_kernel() {
    int gw = (blockIdx.x * blockDim.x + threadIdx.x) >> 5;
    if (gw >= NS) return;
    int lane = threadIdx.x & 31;
    int off = (lane >> 2) * 32 + (lane & 3) * 8;

    int beg = g_offsets[gw];
    int end = g_offsets[gw + 1];

    const float* dfp = g_df + (size_t)gw * 256 + off;
    float4 d0 = *(const float4*)(dfp);
    float4 d1 = *(const float4*)(dfp + 4);

    float m = -1e30f, den = 0.0f;
    float4 a0 = make_float4(0.f, 0.f, 0.f, 0.f);
    float4 a1 = make_float4(0.f, 0.f, 0.f, 0.f);

    int e = beg;
    for (; e + 2 <= end; e += 2) {
        int s0 = __ldg(&g_csr_src[e]);
        int s1 = __ldg(&g_csr_src[e + 1]);
        uint4 rx = __ldg((const uint4*)(g_zf + (size_t)s0 * 256 + off));
        uint4 ry = __ldg((const uint4*)(g_zf + (size_t)s1 * 256 + off));
        const __half2* hx = (const __half2*)&rx;
        const __half2* hy = (const __half2*)&ry;
        float2 xa = __half22float2(hx[0]), xb = __half22float2(hx[1]);
        float2 xc = __half22float2(hx[2]), xd = __half22float2(hx[3]);
        float2 ya = __half22float2(hy[0]), yb = __half22float2(hy[1]);
        float2 yc = __half22float2(hy[2]), yd = __half22float2(hy[3]);
        float4 x0 = make_float4(xa.x, xa.y, xb.x, xb.y);
        float4 x1 = make_float4(xc.x, xc.y, xd.x, xd.y);
        float4 y0 = make_float4(ya.x, ya.y, yb.x, yb.y);
        float4 y1 = make_float4(yc.x, yc.y, yd.x, yd.y);

        float sa = x0.x * d0.x + x0.y * d0.y + x0.z * d0.z + x0.w * d0.w
                 + x1.x * d1.x + x1.y * d1.y + x1.z * d1.z + x1.w * d1.w;
        float sb = y0.x * d0.x + y0.y * d0.y + y0.z * d0.z + y0.w * d0.w
                 + y1.x * d1.x + y1.y * d1.y + y1.z * d1.z + y1.w * d1.w;
        sa += __shfl_xor_sync(0xFFFFFFFFu, sa, 1);
        sb += __shfl_xor_sync(0xFFFFFFFFu, sb, 1);
        sa += __shfl_xor_sync(0xFFFFFFFFu, sa, 2);
        sb += __shfl_xor_sync(0xFFFFFFFFu, sb, 2);

        {
            float mn = fmaxf(m, sa);
            float sc = __expf(m - mn);
            float w  = __expf(sa - mn);
            den = den * sc + w;
            a0.x = a0.x * sc + w * x0.x; a0.y = a0.y * sc + w * x0.y;
            a0.z = a0.z * sc + w * x0.z; a0.w = a0.w * sc + w * x0.w;
            a1.x = a1.x * sc + w * x1.x; a1.y = a1.y * sc + w * x1.y;
            a1.z = a1.z * sc + w * x1.z; a1.w = a1.w * sc + w * x1.w;
            m = mn;
        }
        {
            float mn = fmaxf(m, sb);
            float sc = __expf(m - mn);
            float w  = __expf(sb - mn);
            den = den * sc + w;
            a0.x = a0.x * sc + w * y0.x; a0.y = a0.y * sc + w * y0.y;
            a0.z = a0.z * sc + w * y0.z; a0.w = a0.w * sc + w * y0.w;
            a1.x = a1.x * sc + w * y1.x; a1.y = a1.y * sc + w * y1.y;
            a1.z = a1.z * sc + w * y1.z; a1.w = a1.w * sc + w * y1.w;
            m = mn;
        }
    }
    for (; e < end; e++) {
        int s0 = __ldg(&g_csr_src[e]);
        uint4 rx = __ldg((const uint4*)(g_zf + (size_t)s0 * 256 + off));
        const __half2* hx = (const __half2*)&rx;
        float2 xa = __half22float2(hx[0]), xb = __half22float2(hx[1]);
        float2 xc = __half22float2(hx[2]), xd = __half22float2(hx[3]);
        float4 x0 = make_float4(xa.x, xa.y, xb.x, xb.y);
        float4 x1 = make_float4(xc.x, xc.y, xd.x, xd.y);
        float sa = x0.x * d0.x + x0.y * d0.y + x0.z * d0.z + x0.w * d0.w
                 + x1.x * d1.x + x1.y * d1.y + x1.z * d1.z + x1.w * d1.w;
        sa += __shfl_xor_sync(0xFFFFFFFFu, sa, 1);
        sa += __shfl_xor_sync(0xFFFFFFFFu, sa, 2);
        float mn = fmaxf(m, sa);
        float sc = __expf(m - mn);
        float w  = __expf(sa - mn);
        den = den * sc + w;
        a0.x = a0.x * sc + w * x0.x; a0.y = a0.y * sc + w * x0.y;
        a0.z = a0.z * sc + w * x0.z; a0.w = a0.w * sc + w * x0.w;
        a1.x = a1.x * sc + w * x1.x; a1.y = a1.y * sc + w * x1.y;
        a1.z = a1.z * sc + w * x1.z; a1.w = a1.w * sc + w * x1.w;
        m = mn;
    }

    float inv = 1.0f / den;
    float v[8];
    v[0] = a0.x * inv; v[1] = a0.y * inv; v[2] = a0.z * inv; v[3] = a0.w * inv;
    v[4] = a1.x * inv; v[5] = a1.y * inv; v[6] = a1.z * inv; v[7] = a1.w * inv;
    f16 hv[8];
#pragma unroll
    for (int i = 0; i < 8; i++) {
        v[i] = (v[i] > 0.0f) ? v[i] : expm1f(v[i]);  // ELU(alpha=1)
        hv[i] = __float2half_rn(v[i]);
    }
    size_t ob = (size_t)gw * 256 + off;
    *(uint4*)(g_hf + ob) = make_uint4(pk2(hv[0], hv[1]), pk2(hv[2], hv[3]),
                                      pk2(hv[4], hv[5]), pk2(hv[6], hv[7]));
}

// ---------------- layernorm: warp per row, lane owns 8 contiguous cols ----------------
__global__ void ln_kernel(const float* __restrict__ x,
                          const float* __restrict__ gam,
                          const float* __restrict__ bet) {
    int row = (blockIdx.x * blockDim.x + threadIdx.x) >> 5;
    if (row >= NS) return;
    int lane = threadIdx.x & 31;
    const float* xp = x + (size_t)row * 256 + lane * 8;
    float4 va = *(const float4*)xp;
    float4 vb = *(const float4*)(xp + 4);
    float v[8] = {va.x, va.y, va.z, va.w, vb.x, vb.y, vb.z, vb.w};
    float s = 0.0f, s2 = 0.0f;
#pragma unroll
    for (int r = 0; r < 8; r++) { s += v[r]; s2 += v[r] * v[r]; }
#pragma unroll
    for (int o = 16; o > 0; o >>= 1) {
        s  += __shfl_xor_sync(0xFFFFFFFFu, s, o);
        s2 += __shfl_xor_sync(0xFFFFFFFFu, s2, o);
    }
    float mean = s * (1.0f / 256.0f);
    float var = s2 * (1.0f / 256.0f) - mean * mean;
    float inv = rsqrtf(var + 1e-6f);
    float4 ga = *(const float4*)(gam + lane * 8);
    float4 gb = *(const float4*)(gam + lane * 8 + 4);
    float4 ba = *(const float4*)(bet + lane * 8);
    float4 bb = *(const float4*)(bet + lane * 8 + 4);
    float g[8] = {ga.x, ga.y, ga.z, ga.w, gb.x, gb.y, gb.z, gb.w};
    float bt[8] = {ba.x, ba.y, ba.z, ba.w, bb.x, bb.y, bb.z, bb.w};
    f16 hv[8];
#pragma unroll
    for (int r = 0; r < 8; r++) {
        float y = (v[r] - mean) * inv * g[r] + bt[r];
        hv[r] = __float2half_rn(y);
    }
    size_t ob = (size_t)row * 256 + lane * 8;
    *(uint4*)(g_xnf + ob) = make_uint4(pk2(hv[0], hv[1]), pk2(hv[2], hv[3]),
                                       pk2(hv[4], hv[5]), pk2(hv[6], hv[7]));
}

// ---------------- launch ----------------
extern "C" void kernel_launch(void* const* d_in, const int* in_sizes, int n_in,
                              void* d_out, int out_size) {
    const float* s_in      = (const float*)d_in[0];
    const float* e_in      = (const float*)d_in[1];
    const float* dst_feat  = (const float*)d_in[2];
    const float* fc_w      = (const float*)d_in[3];
    const float* dstfeat_w = (const float*)d_in[4];
    const float* proj_w    = (const float*)d_in[5];
    const float* proj_b    = (const float*)d_in[6];
    const float* ln_g      = (const float*)d_in[7];
    const float* ln_b      = (const float*)d_in[8];
    const float* w1        = (const float*)d_in[9];
    const float* b1        = (const float*)d_in[10];
    const float* w2        = (const float*)d_in[11];
    const float* b2        = (const float*)d_in[12];
    const int*   edge_src  = (const int*)d_in[13];
    const int*   edge_dst  = (const int*)d_in[14];
    float* out = (float*)d_out;

    float *dfp, *xp;
    cudaGetSymbolAddress((void**)&dfp, g_df);
    cudaGetSymbolAddress((void**)&xp,  g_x);
    bf16 *eh, *el, *wzh, *wzl;
    cudaGetSymbolAddress((void**)&eh,  g_eh);  cudaGetSymbolAddress((void**)&el,  g_el);
    cudaGetSymbolAddress((void**)&wzh, g_wzh); cudaGetSymbolAddress((void**)&wzl, g_wzl);
    f16 *zf, *ff, *wd16, *sf, *hf, *xnf, *tf, *pw, *w1p, *w2p;
    cudaGetSymbolAddress((void**)&zf,   g_zf);
    cudaGetSymbolAddress((void**)&ff,   g_ff);
    cudaGetSymbolAddress((void**)&wd16, g_wd16);
    cudaGetSymbolAddress((void**)&sf,   g_sf);
    cudaGetSymbolAddress((void**)&hf,   g_hf);
    cudaGetSymbolAddress((void**)&xnf,  g_xnf);
    cudaGetSymbolAddress((void**)&tf,   g_tf);
    cudaGetSymbolAddress((void**)&pw,   g_pw);
    cudaGetSymbolAddress((void**)&w1p,  g_w1);
    cudaGetSymbolAddress((void**)&w2p,  g_w2);

    cudaFuncSetAttribute(mma_gemm<bf16, 3, 2, 0, false, false, true>,
                         cudaFuncAttributeMaxDynamicSharedMemorySize, SMEM_BF3);
    cudaFuncSetAttribute(mma_gemm<f16, 1, 3, 0, false, false, false>,
                         cudaFuncAttributeMaxDynamicSharedMemorySize, SMEM_FP1);
    cudaFuncSetAttribute(mma_gemm<f16, 1, 3, 0, true, false, false>,
                         cudaFuncAttributeMaxDynamicSharedMemorySize, SMEM_FP1);
    cudaFuncSetAttribute(mma_gemm<f16, 1, 3, 1, true, false, true>,
                         cudaFuncAttributeMaxDynamicSharedMemorySize, SMEM_FP1);
    cudaFuncSetAttribute(mma_gemm<f16, 1, 3, 0, true, true, false>,
                         cudaFuncAttributeMaxDynamicSharedMemorySize, SMEM_FP1);

    const int TB = 256;
    const int MB = (NS + 127) / 128;  // 782

    // ---- side stream for the independent CSR + conversion chain (R14 load) ----
    cudaStream_t s1;
    cudaStreamCreateWithFlags(&s1, cudaStreamNonBlocking);
    cudaEvent_t evFork, evJoin;
    cudaEventCreateWithFlags(&evFork, cudaEventDisableTiming);
    cudaEventCreateWithFlags(&evJoin, cudaEventDisableTiming);

    cudaEventRecord(evFork, 0);
    cudaStreamWaitEvent(s1, evFork, 0);

    // ---- main stream: conversions needed by z/df, then the two pre-softmax GEMMs ----
    act_split_bf<<<(NE * D / 4 + TB - 1) / TB, TB>>>(e_in, eh, el, NE * D);       // 0
    repack_split<<<(256 * 256 + TB - 1) / TB, TB>>>(fc_w, wzh, wzl, 256);         // 1
    act_rn16<<<(NS * FEAT / 4 + TB - 1) / TB, TB>>>(dst_feat, ff, NS * FEAT);     // 2
    // 3: z = e @ Wz  [NE,256] -> fp16 (bf16 3-pass, 2-stage) — ncu capture slot
    mma_gemm<bf16, 3, 2, 0, false, false, true><<<dim3(2, MB), TB, SMEM_BF3>>>(
        eh, el, 256, eh, el, 256, D, wzh, wzl, 256,
        nullptr, nullptr, 0, nullptr, zf, 256, NE, 256);
    repack_rn16<<<(64 * 256 + TB - 1) / TB, TB>>>(dstfeat_w, wd16, 64);           // 4
    // 5: df = dst_feat @ Wd  [NS,256] (fp32 out; fp16 1-pass)
    mma_gemm<f16, 1, 3, 0, false, false, false><<<dim3(2, MB), TB, SMEM_FP1>>>(
        ff, nullptr, 64, ff, nullptr, 64, FEAT, wd16, nullptr, 64,
        nullptr, nullptr, 0, dfp, nullptr, 256, NS, 64);

    // ---- side stream: CSR build + post-softmax-path conversions only ----
    zero_counts<<<(NS + TB - 1) / TB, TB, 0, s1>>>();
    hist_kernel<<<(EDG + TB - 1) / TB, TB, 0, s1>>>(edge_dst);
    scan_pass1<<<NBLK, SCAN_B, 0, s1>>>();
    scan_pass2<<<1, 128, 0, s1>>>();
    scan_pass3<<<NBLK, SCAN_B, 0, s1>>>();
    scatter_kernel<<<(EDG + TB - 1) / TB, TB, 0, s1>>>(edge_src, edge_dst);
    act_rn16<<<(NS * D / 4 + TB - 1) / TB, TB, 0, s1>>>(s_in, sf, NS * D);
    wsplit_t16<<<(512 * 256 + TB - 1) / TB, TB, 0, s1>>>(proj_w, pw, 512, 256);
    wsplit_t16<<<(256 * 512 + TB - 1) / TB, TB, 0, s1>>>(w1, w1p, 256, 512);
    wsplit_t16<<<(512 * 256 + TB - 1) / TB, TB, 0, s1>>>(w2, w2p, 512, 256);
    cudaEventRecord(evJoin, s1);

    cudaStreamWaitEvent(0, evJoin, 0);

    // attention + ELU -> h fp16 rn
    attn_kernel<<<(NS * 32 + TB - 1) / TB, TB>>>();

    // proj: [h | s] @ proj_w + b -> g_x (fp32)  (fp16 1-pass, K=512)
    mma_gemm<f16, 1, 3, 0, true, false, false><<<dim3(2, MB), TB, SMEM_FP1>>>(
        hf, nullptr, 256, sf, nullptr, 256, 256, pw, nullptr, 512,
        proj_b, nullptr, 0, xp, nullptr, 256, NS, 512);

    // layernorm -> xn fp16 rn
    ln_kernel<<<(NS * 32 + TB - 1) / TB, TB>>>(xp, ln_g, ln_b);

    // ffn1: gelu(xn @ w1 + b1) -> t fp16 rn
    mma_gemm<f16, 1, 3, 1, true, false, true><<<dim3(4, MB), TB, SMEM_FP1>>>(
        xnf, nullptr, 256, xnf, nullptr, 256, 256, w1p, nullptr, 256,
        b1, nullptr, 0, nullptr, tf, 512, NS, 256);

    // ffn2: t @ w2 + b2 + g_x -> out (fp32)
    mma_gemm<f16, 1, 3, 0, true, true, false><<<dim3(2, MB), TB, SMEM_FP1>>>(
        tf, nullptr, 512, tf, nullptr, 512, 512, w2p, nullptr, 512,
        b2, xp, 256, out, nullptr, 256, NS, 512);
}

// round 17
// speedup vs baseline: 1.0879x; 1.0322x over previous
#include <cuda_runtime.h>
#include <cuda_fp16.h>
#include <cstdint>
#include <math.h>

// Problem constants (fixed by the dataset)
#define NS 100000
#define NE 100000
#define EDG 1600000
#define D 256
#define H 8
#define HD 32
#define FEAT 64
#define DFF 512

#define SCAN_B 1024
#define NBLK ((NS + SCAN_B - 1) / SCAN_B)   // 98

// smem tile geometry: 32 elems of k per row, padded to 40 (80 B)
#define KP 40
#define ROWB 80
#define MATB (128 * ROWB)          // 10240 B per matrix
#define SMEM_FP1 (3 * 2 * MATB)    // 61440 B: fp16 1-pass, 3 stages (A,B)
#define SMEM_FP2 (3 * 3 * MATB)    // 92160 B: fp16 2-pass, 3 stages (Ah,Al,B)

typedef __half f16;

// ---------------- device scratch (no allocations allowed) ----------------
__device__ f16   g_zf[(size_t)NE * D];   // z in fp16 (gathered by attention)
__device__ float g_df[(size_t)NS * D];
__device__ float g_x[(size_t)NS * D];
// fp16 split e (for z GEMM, 2-pass)
__device__ f16 g_eh[(size_t)NE * D], g_el[(size_t)NE * D];
__device__ f16 g_wz16[256 * 256];        // fc_w transposed fp16
// fp16 rn
__device__ f16 g_ff[(size_t)NS * FEAT];  // dst_feat fp16
__device__ f16 g_wd16[256 * 64];         // dstfeat_w transposed fp16
__device__ f16 g_sf[(size_t)NS * D];
__device__ f16 g_hf[(size_t)NS * D];
__device__ f16 g_xnf[(size_t)NS * D];
__device__ f16 g_tf[(size_t)NS * DFF];
// fp16 plain transposed weights Wt[n][k]
__device__ f16 g_pw[256 * 512];
__device__ f16 g_w1[512 * 256];
__device__ f16 g_w2[256 * 512];
// CSR
__device__ int g_counts[NS];
__device__ int g_offsets[NS + 1];
__device__ int g_cursor[NS];
__device__ int g_csr_src[EDG];
__device__ int g_bsum[NBLK];

// ---------------- small helpers ----------------
__device__ __forceinline__ float gelu_fast(float x) {
    const float c = 0.7978845608028654f;
    float u = c * (x + 0.044715f * x * x * x);
    float e = __expf(2.0f * u);
    float th = 1.0f - 2.0f / (e + 1.0f);
    return 0.5f * x * (1.0f + th);
}
__device__ __forceinline__ uint32_t smem_u32(const void* p) {
    uint32_t a;
    asm("{ .reg .u64 t; cvta.to.shared.u64 t, %1; cvt.u32.u64 %0, t; }" : "=r"(a) : "l"(p));
    return a;
}
__device__ __forceinline__ void ldm_x4(uint32_t* r, uint32_t addr) {
    asm volatile("ldmatrix.sync.aligned.m8n8.x4.shared.b16 {%0,%1,%2,%3}, [%4];"
                 : "=r"(r[0]), "=r"(r[1]), "=r"(r[2]), "=r"(r[3]) : "r"(addr));
}
__device__ __forceinline__ uint32_t pk2(f16 a, f16 b) {
    __half2 t(a, b); return *(uint32_t*)&t;
}
__device__ __forceinline__ void split2h(float x, f16& hi, f16& lo) {
    hi = __float2half_rn(x);
    lo = __float2half_rn(x - __half2float(hi));
}
__device__ __forceinline__ void mma_h(float* c, const uint32_t* a, const uint32_t* b) {
    asm volatile(
        "mma.sync.aligned.m16n8k16.row.col.f32.f16.f16.f32 "
        "{%0,%1,%2,%3}, {%4,%5,%6,%7}, {%8,%9}, {%0,%1,%2,%3};"
        : "+f"(c[0]), "+f"(c[1]), "+f"(c[2]), "+f"(c[3])
        : "r"(a[0]), "r"(a[1]), "r"(a[2]), "r"(a[3]), "r"(b[0]), "r"(b[1]));
}
__device__ __forceinline__ void cpa16(uint32_t dst, const void* src, bool pred) {
    int sz = pred ? 16 : 0;
    asm volatile("cp.async.cg.shared.global [%0], [%1], 16, %2;"
                 :: "r"(dst), "l"(src), "r"(sz) : "memory");
}

// ---------------- conversion kernels ----------------
__global__ void act_split_f16(const float* __restrict__ in, f16* __restrict__ hi,
                              f16* __restrict__ lo, int n) {
    int i = 4 * (blockIdx.x * blockDim.x + threadIdx.x);
    if (i >= n) return;
    float4 v = *(const float4*)(in + i);
    f16 h0, l0, h1, l1, h2, l2, h3, l3;
    split2h(v.x, h0, l0); split2h(v.y, h1, l1);
    split2h(v.z, h2, l2); split2h(v.w, h3, l3);
    *(uint2*)(hi + i) = make_uint2(pk2(h0, h1), pk2(h2, h3));
    *(uint2*)(lo + i) = make_uint2(pk2(l0, l1), pk2(l2, l3));
}
__global__ void act_rn16(const float* __restrict__ in, f16* __restrict__ o, int n) {
    int i = 4 * (blockIdx.x * blockDim.x + threadIdx.x);
    if (i >= n) return;
    float4 v = *(const float4*)(in + i);
    *(uint2*)(o + i) = make_uint2(pk2(__float2half_rn(v.x), __float2half_rn(v.y)),
                                  pk2(__float2half_rn(v.z), __float2half_rn(v.w)));
}
__global__ void wsplit_t16(const float* __restrict__ w, f16* __restrict__ o, int K, int N) {
    int idx = blockIdx.x * blockDim.x + threadIdx.x;
    if (idx >= K * N) return;
    int k = idx / N, n = idx % N;
    o[(size_t)n * K + k] = __float2half_rn(w[idx]);
}
// per-head weight (H, K, HD) -> fp16 rn Wt[256][K]
__global__ void repack_rn16(const float* __restrict__ w, f16* __restrict__ o, int K) {
    int idx = blockIdx.x * blockDim.x + threadIdx.x;
    if (idx >= K * 256) return;
    int n = idx / K, k = idx % K;
    o[idx] = __float2half_rn(w[(n >> 5) * (K * 32) + k * 32 + (n & 31)]);
}

// ================= multistage cp.async fp16 GEMM =================
// PASSES==1: A*B (both fp16 rn). PASSES==2: Ah*B + Al*B (A split hi/lo, B rn).
template <int PASSES, int NSTAGE, int ACT, bool BIAS, bool RES, bool OHALF>
__global__ void __launch_bounds__(256, 2) mma_gemm(
    const f16* __restrict__ Ah0, const f16* __restrict__ Al0, int lda0,
    const f16* __restrict__ Ah1, const f16* __restrict__ Al1, int lda1, int ksplit,
    const f16* __restrict__ B, int ldbk,
    const float* __restrict__ bias,
    const float* __restrict__ res, int ldr,
    float* __restrict__ C, f16* __restrict__ Cf, int ldc,
    int M, int K)
{
    constexpr int NMAT = (PASSES == 2) ? 3 : 2;
    constexpr int STB = NMAT * MATB;
    constexpr int BOFF = (PASSES == 2) ? 2 * MATB : MATB;
    extern __shared__ char dsm[];
    uint32_t sb = smem_u32(dsm);

    int t = threadIdx.x;
    int lane = t & 31, wid = t >> 5;
    int m0 = blockIdx.y * 128;
    int n0 = blockIdx.x * 128;
    int wm = wid & 3;
    int wn = wid >> 2;

    float acc[2][8][4];
#pragma unroll
    for (int i = 0; i < 2; i++)
#pragma unroll
        for (int j = 0; j < 8; j++)
#pragma unroll
            for (int q = 0; q < 4; q++) acc[i][j][q] = 0.0f;

    uint32_t a_off = (uint32_t)(((wm * 32 + (lane & 15)) * KP + (lane >> 4) * 8) * 2);
    uint32_t b_off = (uint32_t)(((wn * 64 + (lane & 7) + (lane >> 4) * 8) * KP
                                 + ((lane >> 3) & 1) * 8) * 2);

    int p_row = t >> 1;
    int p_c0 = (t & 1) * 2;
    bool a_ok = (m0 + p_row) < M;
    const int KT = K >> 5;

    auto prefetch = [&](int kt) {
        if (kt < KT) {
            int k0 = kt * 32;
            int stage = kt % NSTAGE;
            const f16 *AhS, *AlS; int lda, koff;
            if (k0 < ksplit) { AhS = Ah0; AlS = Al0; lda = lda0; koff = k0; }
            else             { AhS = Ah1; AlS = Al1; lda = lda1; koff = k0 - ksplit; }
            const f16* pah = AhS + (size_t)(m0 + p_row) * lda + koff;
            const f16* pb  = B + (size_t)(n0 + p_row) * ldbk + k0;
            uint32_t base = sb + stage * STB + p_row * ROWB;
#pragma unroll
            for (int ci = 0; ci < 2; ci++) {
                int c = p_c0 + ci;
                cpa16(base + c * 16,        pah + c * 8, a_ok);
                cpa16(base + BOFF + c * 16, pb + c * 8, true);
                if (PASSES == 2) {
                    const f16* pal = AlS + (size_t)(m0 + p_row) * lda + koff;
                    cpa16(base + MATB + c * 16, pal + c * 8, a_ok);
                }
            }
        }
        asm volatile("cp.async.commit_group;" ::: "memory");
    };

#pragma unroll
    for (int s = 0; s < NSTAGE - 1; s++) prefetch(s);

    for (int kt = 0; kt < KT; kt++) {
        if (NSTAGE == 2) asm volatile("cp.async.wait_group 0;" ::: "memory");
        else             asm volatile("cp.async.wait_group 1;" ::: "memory");
        __syncthreads();

        prefetch(kt + NSTAGE - 1);

        uint32_t s0 = sb + (kt % NSTAGE) * STB;
        uint32_t sAh = s0, sB = s0 + BOFF;

#pragma unroll
        for (int ks = 0; ks < 2; ks++) {
            uint32_t koffb = (uint32_t)(ks * 32);
            uint32_t a_hi[2][4], b[4][4];
            ldm_x4(a_hi[0], sAh + a_off + koffb);
            ldm_x4(a_hi[1], sAh + a_off + koffb + 16 * KP * 2);
#pragma unroll
            for (int ni2 = 0; ni2 < 4; ni2++)
                ldm_x4(b[ni2], sB + b_off + koffb + ni2 * 16 * KP * 2);
            // pass 1: Ah * B
#pragma unroll
            for (int mi = 0; mi < 2; mi++)
#pragma unroll
                for (int ni = 0; ni < 8; ni++)
                    mma_h(acc[mi][ni], a_hi[mi], &b[ni >> 1][(ni & 1) * 2]);
            if (PASSES == 2) {
                uint32_t sAl = s0 + MATB;
                uint32_t a_lo[2][4];
                ldm_x4(a_lo[0], sAl + a_off + koffb);
                ldm_x4(a_lo[1], sAl + a_off + koffb + 16 * KP * 2);
                // pass 2: Al * B
#pragma unroll
                for (int mi = 0; mi < 2; mi++)
#pragma unroll
                    for (int ni = 0; ni < 8; ni++)
                        mma_h(acc[mi][ni], a_lo[mi], &b[ni >> 1][(ni & 1) * 2]);
            }
        }
    }

    // ---- epilogue ----
#pragma unroll
    for (int mi = 0; mi < 2; mi++) {
#pragma unroll
        for (int ni = 0; ni < 8; ni++) {
            int cc = n0 + wn * 64 + ni * 8 + (lane & 3) * 2;
#pragma unroll
            for (int hh = 0; hh < 2; hh++) {
                int m = m0 + wm * 32 + mi * 16 + (lane >> 2) + hh * 8;
                if (m >= M) continue;
                float v0 = acc[mi][ni][hh * 2 + 0];
                float v1 = acc[mi][ni][hh * 2 + 1];
                if (BIAS) { v0 += bias[cc]; v1 += bias[cc + 1]; }
                if (ACT == 1) { v0 = gelu_fast(v0); v1 = gelu_fast(v1); }
                if (RES) {
                    const float* rp = res + (size_t)m * ldr + cc;
                    v0 += rp[0]; v1 += rp[1];
                }
                if (OHALF) {
                    *(uint32_t*)(Cf + (size_t)m * ldc + cc) =
                        pk2(__float2half_rn(v0), __float2half_rn(v1));
                } else {
                    *(float2*)(C + (size_t)m * ldc + cc) = make_float2(v0, v1);
                }
            }
        }
    }
}

// ---------------- CSR build ----------------
__global__ void zero_counts() {
    int i = blockIdx.x * blockDim.x + threadIdx.x;
    if (i < NS) g_counts[i] = 0;
}
__global__ void hist_kernel(const int* __restrict__ edge_dst) {
    int i = blockIdx.x * blockDim.x + threadIdx.x;
    if (i < EDG) atomicAdd(&g_counts[edge_dst[i]], 1);
}
__global__ void __launch_bounds__(SCAN_B) scan_pass1() {
    __shared__ int ws[32];
    int b = blockIdx.x, t = threadIdx.x;
    int i = b * SCAN_B + t;
    int v = (i < NS) ? g_counts[i] : 0;
#pragma unroll
    for (int o = 16; o; o >>= 1) v += __shfl_xor_sync(0xFFFFFFFFu, v, o);
    if ((t & 31) == 0) ws[t >> 5] = v;
    __syncthreads();
    if (t < 32) {
        int x = ws[t];
#pragma unroll
        for (int o = 16; o; o >>= 1) x += __shfl_xor_sync(0xFFFFFFFFu, x, o);
        if (t == 0) g_bsum[b] = x;
    }
}
__global__ void scan_pass2() {
    __shared__ int sh[128];
    int t = threadIdx.x;
    int orig = (t < NBLK) ? g_bsum[t] : 0;
    sh[t] = orig;
    __syncthreads();
    for (int o = 1; o < 128; o <<= 1) {
        int v = (t >= o) ? sh[t - o] : 0;
        __syncthreads();
        sh[t] += v;
        __syncthreads();
    }
    if (t < NBLK) g_bsum[t] = sh[t] - orig;
}
__global__ void __launch_bounds__(SCAN_B) scan_pass3() {
    __shared__ int ws[32];
    int b = blockIdx.x, t = threadIdx.x;
    int lane = t & 31, w = t >> 5;
    int i = b * SCAN_B + t;
    int v = (i < NS) ? g_counts[i] : 0;
    int x = v;
#pragma unroll
    for (int o = 1; o < 32; o <<= 1) {
        int y = __shfl_up_sync(0xFFFFFFFFu, x, o);
        if (lane >= o) x += y;
    }
    if (lane == 31) ws[w] = x;
    __syncthreads();
    if (w == 0) {
        int sv = ws[lane];
#pragma unroll
        for (int o = 1; o < 32; o <<= 1) {
            int y = __shfl_up_sync(0xFFFFFFFFu, sv, o);
            if (lane >= o) sv += y;
        }
        ws[lane] = sv;
    }
    __syncthreads();
    int incl = x + (w > 0 ? ws[w - 1] : 0) + g_bsum[b];
    if (i < NS) {
        g_offsets[i + 1] = incl;
        g_cursor[i] = incl - v;
    }
    if (b == 0 && t == 0) g_offsets[0] = 0;
}
__global__ void scatter_kernel(const int* __restrict__ edge_src,
                               const int* __restrict__ edge_dst) {
    int i = blockIdx.x * blockDim.x + threadIdx.x;
    if (i >= EDG) return;
    int dst = edge_dst[i];
    int pos = atomicAdd(&g_cursor[dst], 1);
    g_csr_src[pos] = edge_src[i];
}

// ---------------- attention: warp per dst, lane = (head, quarter) ----------------
__global__ void __launch_bounds__(256) attn_kernel() {
    int gw = (blockIdx.x * blockDim.x + threadIdx.x) >> 5;
    if (gw >= NS) return;
    int lane = threadIdx.x & 31;
    int off = (lane >> 2) * 32 + (lane & 3) * 8;

    int beg = g_offsets[gw];
    int end = g_offsets[gw + 1];

    const float* dfp = g_df + (size_t)gw * 256 + off;
    float4 d0 = *(const float4*)(dfp);
    float4 d1 = *(const float4*)(dfp + 4);

    float m = -1e30f, den = 0.0f;
    float4 a0 = make_float4(0.f, 0.f, 0.f, 0.f);
    float4 a1 = make_float4(0.f, 0.f, 0.f, 0.f);

    int e = beg;
    for (; e + 2 <= end; e += 2) {
        int s0 = __ldg(&g_csr_src[e]);
        int s1 = __ldg(&g_csr_src[e + 1]);
        uint4 rx = __ldg((const uint4*)(g_zf + (size_t)s0 * 256 + off));
        uint4 ry = __ldg((const uint4*)(g_zf + (size_t)s1 * 256 + off));
        const __half2* hx = (const __half2*)&rx;
        const __half2* hy = (const __half2*)&ry;
        float2 xa = __half22float2(hx[0]), xb = __half22float2(hx[1]);
        float2 xc = __half22float2(hx[2]), xd = __half22float2(hx[3]);
        float2 ya = __half22float2(hy[0]), yb = __half22float2(hy[1]);
        float2 yc = __half22float2(hy[2]), yd = __half22float2(hy[3]);
        float4 x0 = make_float4(xa.x, xa.y, xb.x, xb.y);
        float4 x1 = make_float4(xc.x, xc.y, xd.x, xd.y);
        float4 y0 = make_float4(ya.x, ya.y, yb.x, yb.y);
        float4 y1 = make_float4(yc.x, yc.y, yd.x, yd.y);

        float sa = x0.x * d0.x + x0.y * d0.y + x0.z * d0.z + x0.w * d0.w
                 + x1.x * d1.x + x1.y * d1.y + x1.z * d1.z + x1.w * d1.w;
        float sb = y0.x * d0.x + y0.y * d0.y + y0.z * d0.z + y0.w * d0.w
                 + y1.x * d1.x + y1.y * d1.y + y1.z * d1.z + y1.w * d1.w;
        sa += __shfl_xor_sync(0xFFFFFFFFu, sa, 1);
        sb += __shfl_xor_sync(0xFFFFFFFFu, sb, 1);
        sa += __shfl_xor_sync(0xFFFFFFFFu, sa, 2);
        sb += __shfl_xor_sync(0xFFFFFFFFu, sb, 2);

        {
            float mn = fmaxf(m, sa);
            float sc = __expf(m - mn);
            float w  = __expf(sa - mn);
            den = den * sc + w;
            a0.x = a0.x * sc + w * x0.x; a0.y = a0.y * sc + w * x0.y;
            a0.z = a0.z * sc + w * x0.z; a0.w = a0.w * sc + w * x0.w;
            a1.x = a1.x * sc + w * x1.x; a1.y = a1.y * sc + w * x1.y;
            a1.z = a1.z * sc + w * x1.z; a1.w = a1.w * sc + w * x1.w;
            m = mn;
        }
        {
            float mn = fmaxf(m, sb);
            float sc = __expf(m - mn);
            float w  = __expf(sb - mn);
            den = den * sc + w;
            a0.x = a0.x * sc + w * y0.x; a0.y = a0.y * sc + w * y0.y;
            a0.z = a0.z * sc + w * y0.z; a0.w = a0.w * sc + w * y0.w;
            a1.x = a1.x * sc + w * y1.x; a1.y = a1.y * sc + w * y1.y;
            a1.z = a1.z * sc + w * y1.z; a1.w = a1.w * sc + w * y1.w;
            m = mn;
        }
    }
    for (; e < end; e++) {
        int s0 = __ldg(&g_csr_src[e]);
        uint4 rx = __ldg((const uint4*)(g_zf + (size_t)s0 * 256 + off));
        const __half2* hx = (const __half2*)&rx;
        float2 xa = __half22float2(hx[0]), xb = __half22float2(hx[1]);
        float2 xc = __half22float2(hx[2]), xd = __half22float2(hx[3]);
        float4 x0 = make_float4(xa.x, xa.y, xb.x, xb.y);
        float4 x1 = make_float4(xc.x, xc.y, xd.x, xd.y);
        float sa = x0.x * d0.x + x0.y * d0.y + x0.z * d0.z + x0.w * d0.w
                 + x1.x * d1.x + x1.y * d1.y + x1.z * d1.z + x1.w * d1.w;
        sa += __shfl_xor_sync(0xFFFFFFFFu, sa, 1);
        sa += __shfl_xor_sync(0xFFFFFFFFu, sa, 2);
        float mn = fmaxf(m, sa);
        float sc = __expf(m - mn);
        float w  = __expf(sa - mn);
        den = den * sc + w;
        a0.x = a0.x * sc + w * x0.x; a0.y = a0.y * sc + w * x0.y;
        a0.z = a0.z * sc + w * x0.z; a0.w = a0.w * sc + w * x0.w;
        a1.x = a1.x * sc + w * x1.x; a1.y = a1.y * sc + w * x1.y;
        a1.z = a1.z * sc + w * x1.z; a1.w = a1.w * sc + w * x1.w;
        m = mn;
    }

    float inv = 1.0f / den;
    float v[8];
    v[0] = a0.x * inv; v[1] = a0.y * inv; v[2] = a0.z * inv; v[3] = a0.w * inv;
    v[4] = a1.x * inv; v[5] = a1.y * inv; v[6] = a1.z * inv; v[7] = a1.w * inv;
    f16 hv[8];
#pragma unroll
    for (int i = 0; i < 8; i++) {
        v[i] = (v[i] > 0.0f) ? v[i] : expm1f(v[i]);  // ELU(alpha=1)
        hv[i] = __float2half_rn(v[i]);
    }
    size_t ob = (size_t)gw * 256 + off;
    *(uint4*)(g_hf + ob) = make_uint4(pk2(hv[0], hv[1]), pk2(hv[2], hv[3]),
                                      pk2(hv[4], hv[5]), pk2(hv[6], hv[7]));
}

// ---------------- layernorm: warp per row, lane owns 8 contiguous cols ----------------
__global__ void ln_kernel(const float* __restrict__ x,
                          const float* __restrict__ gam,
                          const float* __restrict__ bet) {
    int row = (blockIdx.x * blockDim.x + threadIdx.x) >> 5;
    if (row >= NS) return;
    int lane = threadIdx.x & 31;
    const float* xp = x + (size_t)row * 256 + lane * 8;
    float4 va = *(const float4*)xp;
    float4 vb = *(const float4*)(xp + 4);
    float v[8] = {va.x, va.y, va.z, va.w, vb.x, vb.y, vb.z, vb.w};
    float s = 0.0f, s2 = 0.0f;
#pragma unroll
    for (int r = 0; r < 8; r++) { s += v[r]; s2 += v[r] * v[r]; }
#pragma unroll
    for (int o = 16; o > 0; o >>= 1) {
        s  += __shfl_xor_sync(0xFFFFFFFFu, s, o);
        s2 += __shfl_xor_sync(0xFFFFFFFFu, s2, o);
    }
    float mean = s * (1.0f / 256.0f);
    float var = s2 * (1.0f / 256.0f) - mean * mean;
    float inv = rsqrtf(var + 1e-6f);
    float4 ga = *(const float4*)(gam + lane * 8);
    float4 gb = *(const float4*)(gam + lane * 8 + 4);
    float4 ba = *(const float4*)(bet + lane * 8);
    float4 bb = *(const float4*)(bet + lane * 8 + 4);
    float g[8] = {ga.x, ga.y, ga.z, ga.w, gb.x, gb.y, gb.z, gb.w};
    float bt[8] = {ba.x, ba.y, ba.z, ba.w, bb.x, bb.y, bb.z, bb.w};
    f16 hv[8];
#pragma unroll
    for (int r = 0; r < 8; r++) {
        float y = (v[r] - mean) * inv * g[r] + bt[r];
        hv[r] = __float2half_rn(y);
    }
    size_t ob = (size_t)row * 256 + lane * 8;
    *(uint4*)(g_xnf + ob) = make_uint4(pk2(hv[0], hv[1]), pk2(hv[2], hv[3]),
                                       pk2(hv[4], hv[5]), pk2(hv[6], hv[7]));
}

// ---------------- launch ----------------
extern "C" void kernel_launch(void* const* d_in, const int* in_sizes, int n_in,
                              void* d_out, int out_size) {
    const float* s_in      = (const float*)d_in[0];
    const float* e_in      = (const float*)d_in[1];
    const float* dst_feat  = (const float*)d_in[2];
    const float* fc_w      = (const float*)d_in[3];
    const float* dstfeat_w = (const float*)d_in[4];
    const float* proj_w    = (const float*)d_in[5];
    const float* proj_b    = (const float*)d_in[6];
    const float* ln_g      = (const float*)d_in[7];
    const float* ln_b      = (const float*)d_in[8];
    const float* w1        = (const float*)d_in[9];
    const float* b1        = (const float*)d_in[10];
    const float* w2        = (const float*)d_in[11];
    const float* b2        = (const float*)d_in[12];
    const int*   edge_src  = (const int*)d_in[13];
    const int*   edge_dst  = (const int*)d_in[14];
    float* out = (float*)d_out;

    float *dfp, *xp;
    cudaGetSymbolAddress((void**)&dfp, g_df);
    cudaGetSymbolAddress((void**)&xp,  g_x);
    f16 *zf, *eh, *el, *wz16, *ff, *wd16, *sf, *hf, *xnf, *tf, *pw, *w1p, *w2p;
    cudaGetSymbolAddress((void**)&zf,   g_zf);
    cudaGetSymbolAddress((void**)&eh,   g_eh);
    cudaGetSymbolAddress((void**)&el,   g_el);
    cudaGetSymbolAddress((void**)&wz16, g_wz16);
    cudaGetSymbolAddress((void**)&ff,   g_ff);
    cudaGetSymbolAddress((void**)&wd16, g_wd16);
    cudaGetSymbolAddress((void**)&sf,   g_sf);
    cudaGetSymbolAddress((void**)&hf,   g_hf);
    cudaGetSymbolAddress((void**)&xnf,  g_xnf);
    cudaGetSymbolAddress((void**)&tf,   g_tf);
    cudaGetSymbolAddress((void**)&pw,   g_pw);
    cudaGetSymbolAddress((void**)&w1p,  g_w1);
    cudaGetSymbolAddress((void**)&w2p,  g_w2);

    cudaFuncSetAttribute(mma_gemm<2, 3, 0, false, false, true>,
                         cudaFuncAttributeMaxDynamicSharedMemorySize, SMEM_FP2);
    cudaFuncSetAttribute(mma_gemm<1, 3, 0, false, false, false>,
                         cudaFuncAttributeMaxDynamicSharedMemorySize, SMEM_FP1);
    cudaFuncSetAttribute(mma_gemm<1, 3, 0, true, false, false>,
                         cudaFuncAttributeMaxDynamicSharedMemorySize, SMEM_FP1);
    cudaFuncSetAttribute(mma_gemm<1, 3, 1, true, false, true>,
                         cudaFuncAttributeMaxDynamicSharedMemorySize, SMEM_FP1);
    cudaFuncSetAttribute(mma_gemm<1, 3, 0, true, true, false>,
                         cudaFuncAttributeMaxDynamicSharedMemorySize, SMEM_FP1);

    const int TB = 256;
    const int MB = (NS + 127) / 128;  // 782

    // ---- side stream for the independent CSR + conversion chain (R14/R16 load) ----
    cudaStream_t s1;
    cudaStreamCreateWithFlags(&s1, cudaStreamNonBlocking);
    cudaEvent_t evFork, evJoin;
    cudaEventCreateWithFlags(&evFork, cudaEventDisableTiming);
    cudaEventCreateWithFlags(&evJoin, cudaEventDisableTiming);

    cudaEventRecord(evFork, 0);
    cudaStreamWaitEvent(s1, evFork, 0);

    // ---- main stream: conversions needed by z/df, then the two pre-softmax GEMMs ----
    act_split_f16<<<(NE * D / 4 + TB - 1) / TB, TB>>>(e_in, eh, el, NE * D);      // 0
    repack_rn16<<<(256 * 256 + TB - 1) / TB, TB>>>(fc_w, wz16, 256);              // 1
    act_rn16<<<(NS * FEAT / 4 + TB - 1) / TB, TB>>>(dst_feat, ff, NS * FEAT);     // 2
    // 3: z = e @ Wz  [NE,256] -> fp16 (fp16 2-pass, 3-stage) — ncu capture slot
    mma_gemm<2, 3, 0, false, false, true><<<dim3(2, MB), TB, SMEM_FP2>>>(
        eh, el, 256, eh, el, 256, D, wz16, 256,
        nullptr, nullptr, 0, nullptr, zf, 256, NE, 256);
    repack_rn16<<<(64 * 256 + TB - 1) / TB, TB>>>(dstfeat_w, wd16, 64);           // 4
    // 5: df = dst_feat @ Wd  [NS,256] (fp32 out; fp16 1-pass)
    mma_gemm<1, 3, 0, false, false, false><<<dim3(2, MB), TB, SMEM_FP1>>>(
        ff, nullptr, 64, ff, nullptr, 64, FEAT, wd16, 64,
        nullptr, nullptr, 0, dfp, nullptr, 256, NS, 64);

    // ---- side stream: CSR build + post-softmax-path conversions only ----
    zero_counts<<<(NS + TB - 1) / TB, TB, 0, s1>>>();
    hist_kernel<<<(EDG + TB - 1) / TB, TB, 0, s1>>>(edge_dst);
    scan_pass1<<<NBLK, SCAN_B, 0, s1>>>();
    scan_pass2<<<1, 128, 0, s1>>>();
    scan_pass3<<<NBLK, SCAN_B, 0, s1>>>();
    scatter_kernel<<<(EDG + TB - 1) / TB, TB, 0, s1>>>(edge_src, edge_dst);
    act_rn16<<<(NS * D / 4 + TB - 1) / TB, TB, 0, s1>>>(s_in, sf, NS * D);
    wsplit_t16<<<(512 * 256 + TB - 1) / TB, TB, 0, s1>>>(proj_w, pw, 512, 256);
    wsplit_t16<<<(256 * 512 + TB - 1) / TB, TB, 0, s1>>>(w1, w1p, 256, 512);
    wsplit_t16<<<(512 * 256 + TB - 1) / TB, TB, 0, s1>>>(w2, w2p, 512, 256);
    cudaEventRecord(evJoin, s1);

    cudaStreamWaitEvent(0, evJoin, 0);

    // attention + ELU -> h fp16 rn
    attn_kernel<<<(NS * 32 + TB - 1) / TB, TB>>>();

    // proj: [h | s] @ proj_w + b -> g_x (fp32)  (fp16 1-pass, K=512)
    mma_gemm<1, 3, 0, true, false, false><<<dim3(2, MB), TB, SMEM_FP1>>>(
        hf, nullptr, 256, sf, nullptr, 256, 256, pw, 512,
        proj_b, nullptr, 0, xp, nullptr, 256, NS, 512);

    // layernorm -> xn fp16 rn
    ln_kernel<<<(NS * 32 + TB - 1) / TB, TB>>>(xp, ln_g, ln_b);

    // ffn1: gelu(xn @ w1 + b1) -> t fp16 rn
    mma_gemm<1, 3, 1, true, false, true><<<dim3(4, MB), TB, SMEM_FP1>>>(
        xnf, nullptr, 256, xnf, nullptr, 256, 256, w1p, 256,
        b1, nullptr, 0, nullptr, tf, 512, NS, 256);

    // ffn2: t @ w2 + b2 + g_x -> out (fp32)
    mma_gemm<1, 3, 0, true, true, false><<<dim3(2, MB), TB, SMEM_FP1>>>(
        tf, nullptr, 512, tf, nullptr, 512, 512, w2p, 512,
        b2, xp, 256, out, nullptr, 256, NS, 512);
}